// round 15
// baseline (speedup 1.0000x reference)
#include <cuda_runtime.h>
#include <cuda_bf16.h>
#include <cuda_fp16.h>
#include <math.h>
#include <stdint.h>

#define B_  2
#define S_  2048
#define D_  1024
#define H_  16
#define HD_ 64

typedef __nv_bfloat16 bf16;

// ---------------- scratch (no cudaMalloc allowed) ----------------
__device__ __half g_xf[(size_t)B_ * S_ * D_];                             // x fp16 single
__device__ __half g_Wfh[(size_t)4 * D_ * D_], g_Wfl[(size_t)4 * D_ * D_]; // Wq,k,v,o fp16 hi/lo
__device__ float g_bias3[3 * D_];
__device__ __half g_QKVh[(size_t)B_ * S_ * 3 * D_], g_QKVl[(size_t)B_ * S_ * 3 * D_];
__device__ __half g_cf[(size_t)B_ * S_ * D_];                             // ctx fp16 single
__device__ __half g_P[(size_t)B_ * H_ * S_ * S_];       // attn probs fp16
__device__ __half g_scores[(size_t)B_ * H_ * S_ * S_];  // scores fp16 (268 MB)

// ======================= PTX helpers =======================
__device__ __forceinline__ uint32_t sptr(const void* p) {
    return (uint32_t)__cvta_generic_to_shared(p);
}
__device__ __forceinline__ void cpa16(uint32_t dst, const void* src) {
    asm volatile("cp.async.cg.shared.global [%0], [%1], 16;" :: "r"(dst), "l"(src));
}
__device__ __forceinline__ void cpa_commit() {
    asm volatile("cp.async.commit_group;");
}
template<int N> __device__ __forceinline__ void cpa_wait() {
    asm volatile("cp.async.wait_group %0;" :: "n"(N));
}
__device__ __forceinline__ void ldm_x4(uint32_t (&r)[4], uint32_t addr) {
    asm volatile("ldmatrix.sync.aligned.m8n8.x4.shared.b16 {%0,%1,%2,%3}, [%4];"
                 : "=r"(r[0]), "=r"(r[1]), "=r"(r[2]), "=r"(r[3]) : "r"(addr));
}
__device__ __forceinline__ void ldm_x4t(uint32_t (&r)[4], uint32_t addr) {
    asm volatile("ldmatrix.sync.aligned.m8n8.x4.trans.shared.b16 {%0,%1,%2,%3}, [%4];"
                 : "=r"(r[0]), "=r"(r[1]), "=r"(r[2]), "=r"(r[3]) : "r"(addr));
}
__device__ __forceinline__ void mma_fp16(float (&c)[4], const uint32_t (&a)[4],
                                         uint32_t b0, uint32_t b1) {
    asm volatile(
        "mma.sync.aligned.m16n8k16.row.col.f32.f16.f16.f32 "
        "{%0,%1,%2,%3}, {%4,%5,%6,%7}, {%8,%9}, {%0,%1,%2,%3};"
        : "+f"(c[0]), "+f"(c[1]), "+f"(c[2]), "+f"(c[3])
        : "r"(a[0]), "r"(a[1]), "r"(a[2]), "r"(a[3]), "r"(b0), "r"(b1));
}
__device__ __forceinline__ void splitu_fp16(float x, uint16_t& h, uint16_t& l) {
    __half hh = __float2half(x);
    __half ll = __float2half(x - __half2float(hh));
    h = *(uint16_t*)&hh; l = *(uint16_t*)&ll;
}

// ======================================================================
// split / bias kernels
// ======================================================================
__global__ void __launch_bounds__(256)
split_query(const float* __restrict__ x, __half* __restrict__ xf)
{
    size_t i = (size_t)blockIdx.x * 256 + threadIdx.x;
    xf[i] = __float2half(x[i]);
}

__global__ void __launch_bounds__(256)
split_weights(const float* __restrict__ Wq, const float* __restrict__ Wk,
              const float* __restrict__ Wv, const float* __restrict__ Wo,
              __half* __restrict__ Wfh, __half* __restrict__ Wfl)
{
    size_t i = (size_t)blockIdx.x * 256 + threadIdx.x;   // < D*D
    const size_t n = (size_t)D_ * D_;
    uint16_t h, l;
    splitu_fp16(Wq[i], h, l); Wfh[i]       = *(__half*)&h; Wfl[i]       = *(__half*)&l;
    splitu_fp16(Wk[i], h, l); Wfh[i + n]   = *(__half*)&h; Wfl[i + n]   = *(__half*)&l;
    splitu_fp16(Wv[i], h, l); Wfh[i + 2*n] = *(__half*)&h; Wfl[i + 2*n] = *(__half*)&l;
    splitu_fp16(Wo[i], h, l); Wfh[i + 3*n] = *(__half*)&h; Wfl[i + 3*n] = *(__half*)&l;
}

__global__ void __launch_bounds__(256)
concat_bias(const float* __restrict__ a, const float* __restrict__ b,
            const float* __restrict__ c, float* __restrict__ o)
{
    int i = blockIdx.x * 256 + threadIdx.x;   // < D_
    o[i] = a[i]; o[D_ + i] = b[i]; o[2 * D_ + i] = c[i];
}

// ======================================================================
// fp16x2 GEMM: C = alpha*A*B^T (+bias). A fp16 single [M,K], B fp16 hi/lo.
// 2 MMAs per tile (A*Bh + A*Bl). k-chunk 32, 2 stages, proven-safe loop.
// 256 thr, 8 warps (2x4), warp 64x32. Stage 30720B: A@0, BH@10240, BL@20480.
// Output: fp32 Cf (+bias), OR fp16 single C16, OR fp16 hi/lo split Coh/Col.
// Batched via zdiv / strides.
// ======================================================================
#define F2_STG  30720
#define F2_SMEM (2 * F2_STG)

__global__ void __launch_bounds__(256)
gemm_nt_f16(const __half* __restrict__ Ag, int lda,
            const __half* __restrict__ Bgh, const __half* __restrict__ Bgl, int ldb,
            float* __restrict__ Cf, __half* __restrict__ C16,
            __half* __restrict__ Coh, __half* __restrict__ Col,
            int ldc, int K, float alpha, const float* __restrict__ bias,
            int zdiv,
            size_t sA1, size_t sA2, size_t sB1, size_t sB2, size_t sC1, size_t sC2)
{
    extern __shared__ char dsm[];
    int z = blockIdx.z;
    int z1 = z / zdiv, z2 = z % zdiv;
    Ag  += z1 * sA1 + z2 * sA2;
    Bgh += z1 * sB1 + z2 * sB2;  Bgl += z1 * sB1 + z2 * sB2;
    size_t coff = z1 * sC1 + z2 * sC2;

    const uint32_t sb = sptr(dsm);
    const int bm = blockIdx.y * 128;
    const int bn = blockIdx.x * 128;
    const int tid = threadIdx.x;
    const int warp = tid >> 5, lane = tid & 31;
    const int wm = warp >> 2, wn = warp & 3;

    float acc[4][4][4];
#pragma unroll
    for (int i = 0; i < 4; i++)
#pragma unroll
        for (int j = 0; j < 4; j++)
#pragma unroll
            for (int l = 0; l < 4; l++) acc[i][j][l] = 0.f;

    const int KT = K >> 5;

    auto issue = [&](int kt, int st) {
        uint32_t base = sb + st * F2_STG;
        int k0 = kt * 32;
#pragma unroll
        for (int i = 0; i < 6; i++) {
            int ch = i * 256 + tid;               // 0..1535
            int arr = ch >> 9;                    // 0=A 1=BH 2=BL
            int row = (ch & 511) >> 2;
            int c16 = ch & 3;
            uint32_t dst = base + arr * 10240 + row * 80 + c16 * 16;
            const __half* src;
            int col = k0 + c16 * 8;
            if (arr == 0)      src = Ag  + (size_t)(bm + row) * lda + col;
            else if (arr == 1) src = Bgh + (size_t)(bn + row) * ldb + col;
            else               src = Bgl + (size_t)(bn + row) * ldb + col;
            cpa16(dst, src);
        }
        cpa_commit();
    };

    issue(0, 0);

    for (int kt = 0; kt < KT; kt++) {
        int st = kt & 1;
        if (kt + 1 < KT) { issue(kt + 1, st ^ 1); cpa_wait<1>(); }
        else             { cpa_wait<0>(); }
        __syncthreads();

        uint32_t base = sb + st * F2_STG;
#pragma unroll
        for (int ks = 0; ks < 2; ks++) {
            uint32_t ah[4][4];
            {
                int arow = wm * 64 + (lane & 15);
                uint32_t ac = ks * 32 + (lane >> 4) * 16;
#pragma unroll
                for (int mt = 0; mt < 4; mt++)
                    ldm_x4(ah[mt], base + (uint32_t)(arow + mt * 16) * 80 + ac);
            }
            uint32_t bh[2][4], bl[2][4];
            {
                int brow0 = wn * 32 + (lane & 7) + ((lane >> 4) & 1) * 8;
                uint32_t bc = ((lane >> 3) & 1) * 16 + ks * 32;
#pragma unroll
                for (int pr = 0; pr < 2; pr++) {
                    uint32_t ro = (uint32_t)(brow0 + pr * 16) * 80 + bc;
                    ldm_x4(bh[pr], base + 10240 + ro);
                    ldm_x4(bl[pr], base + 20480 + ro);
                }
            }
#pragma unroll
            for (int mt = 0; mt < 4; mt++)
#pragma unroll
                for (int nt = 0; nt < 4; nt++) {
                    uint32_t b0h = bh[nt >> 1][(nt & 1) * 2];
                    uint32_t b1h = bh[nt >> 1][(nt & 1) * 2 + 1];
                    uint32_t b0l = bl[nt >> 1][(nt & 1) * 2];
                    uint32_t b1l = bl[nt >> 1][(nt & 1) * 2 + 1];
                    mma_fp16(acc[mt][nt], ah[mt], b0h, b1h);
                    mma_fp16(acc[mt][nt], ah[mt], b0l, b1l);
                }
        }
        __syncthreads();
    }

    const int g = lane >> 2, tig = lane & 3;
#pragma unroll
    for (int mt = 0; mt < 4; mt++) {
#pragma unroll
        for (int nt = 0; nt < 4; nt++) {
            int row = bm + wm * 64 + mt * 16 + g;
            int col = bn + wn * 32 + nt * 8 + tig * 2;
            float b0 = bias ? bias[col] : 0.f;
            float b1 = bias ? bias[col + 1] : 0.f;
            float v00 = alpha * acc[mt][nt][0] + b0;
            float v01 = alpha * acc[mt][nt][1] + b1;
            float v10 = alpha * acc[mt][nt][2] + b0;
            float v11 = alpha * acc[mt][nt][3] + b1;
            size_t o0 = coff + (size_t)row * ldc + col;
            size_t o1 = coff + (size_t)(row + 8) * ldc + col;
            if (Cf) {
                *(float2*)&Cf[o0] = make_float2(v00, v01);
                *(float2*)&Cf[o1] = make_float2(v10, v11);
            } else if (C16) {
                __half2 p0 = __floats2half2_rn(v00, v01);
                __half2 p1 = __floats2half2_rn(v10, v11);
                *(uint32_t*)&C16[o0] = *(uint32_t*)&p0;
                *(uint32_t*)&C16[o1] = *(uint32_t*)&p1;
            } else {
                uint16_t h0, l0, h1, l1;
                splitu_fp16(v00, h0, l0); splitu_fp16(v01, h1, l1);
                *(uint32_t*)&Coh[o0] = (uint32_t)h0 | ((uint32_t)h1 << 16);
                *(uint32_t*)&Col[o0] = (uint32_t)l0 | ((uint32_t)l1 << 16);
                splitu_fp16(v10, h0, l0); splitu_fp16(v11, h1, l1);
                *(uint32_t*)&Coh[o1] = (uint32_t)h0 | ((uint32_t)h1 << 16);
                *(uint32_t*)&Col[o1] = (uint32_t)l0 | ((uint32_t)l1 << 16);
            }
        }
    }
}

// ======================================================================
// PV GEMM: ctx = P @ V. P fp16 single, V fp16 hi/lo. 2 MMAs per tile.
// k-chunk 32, 2 stages, proven-safe loop. 8 warps (4x2), warp 32x32.
// Stage (19456B): P@0 (128x80B), VH@10240 (32x144B), VL@14848.
// Output: ctx fp16 single.
// ======================================================================
#define NN_STG  19456
#define NN_SMEM (2 * NN_STG)

__global__ void __launch_bounds__(256)
gemm_pv(const __half* __restrict__ P, int lda,
        const __half* __restrict__ Vgh, const __half* __restrict__ Vgl, int ldb,
        __half* __restrict__ Co, int ldc,
        int K, int zdiv,
        size_t sA1, size_t sA2, size_t sB1, size_t sB2, size_t sC1, size_t sC2)
{
    extern __shared__ char dsm[];
    int z = blockIdx.z;
    int z1 = z / zdiv, z2 = z % zdiv;
    P   += z1 * sA1 + z2 * sA2;
    Vgh += z1 * sB1 + z2 * sB2;  Vgl += z1 * sB1 + z2 * sB2;
    size_t coff = z1 * sC1 + z2 * sC2;

    const uint32_t sb = sptr(dsm);
    const int bm = blockIdx.y * 128;
    const int tid = threadIdx.x;
    const int warp = tid >> 5, lane = tid & 31;
    const int wm = warp >> 1, wn = warp & 1;

    float acc[2][4][4];
#pragma unroll
    for (int i = 0; i < 2; i++)
#pragma unroll
        for (int j = 0; j < 4; j++)
#pragma unroll
            for (int l = 0; l < 4; l++) acc[i][j][l] = 0.f;

    const int KT = K >> 5;

    auto issue = [&](int kt, int st) {
        uint32_t base = sb + st * NN_STG;
        int k0 = kt * 32;
#pragma unroll
        for (int i = 0; i < 2; i++) {
            int ch = i * 256 + tid;
            int row = ch >> 2, c16 = ch & 3;
            const __half* src = P + (size_t)(bm + row) * lda + k0 + c16 * 8;
            cpa16(base + row * 80 + c16 * 16, src);
        }
#pragma unroll
        for (int i = 0; i < 2; i++) {
            int ch = i * 256 + tid;
            int arr = ch >> 8, row = (ch & 255) >> 3, c16 = ch & 7;
            const __half* src = (arr ? Vgl : Vgh) + (size_t)(k0 + row) * ldb + c16 * 8;
            cpa16(base + 10240 + arr * 4608 + row * 144 + c16 * 16, src);
        }
        cpa_commit();
    };

    issue(0, 0);

    for (int kt = 0; kt < KT; kt++) {
        int st = kt & 1;
        if (kt + 1 < KT) { issue(kt + 1, st ^ 1); cpa_wait<1>(); }
        else             { cpa_wait<0>(); }
        __syncthreads();

        uint32_t base = sb + st * NN_STG;
#pragma unroll
        for (int ks = 0; ks < 2; ks++) {
            uint32_t ah[2][4];
            {
                int arow = wm * 32 + (lane & 15);
                uint32_t ac = ks * 32 + (lane >> 4) * 16;
#pragma unroll
                for (int mt = 0; mt < 2; mt++)
                    ldm_x4(ah[mt], base + (uint32_t)(arow + mt * 16) * 80 + ac);
            }
            uint32_t bh[2][4], bl[2][4];
            {
                int l16 = lane & 15, hi = lane >> 4;
                uint32_t rowoff = (uint32_t)(ks * 16 + l16) * 144;
#pragma unroll
                for (int pr = 0; pr < 2; pr++) {
                    uint32_t co = (wn * 32 + pr * 16 + hi * 8) * 2;
                    ldm_x4t(bh[pr], base + 10240 + rowoff + co);
                    ldm_x4t(bl[pr], base + 14848 + rowoff + co);
                }
            }
#pragma unroll
            for (int mt = 0; mt < 2; mt++)
#pragma unroll
                for (int nt = 0; nt < 4; nt++) {
                    uint32_t b0h = bh[nt >> 1][(nt & 1) * 2];
                    uint32_t b1h = bh[nt >> 1][(nt & 1) * 2 + 1];
                    uint32_t b0l = bl[nt >> 1][(nt & 1) * 2];
                    uint32_t b1l = bl[nt >> 1][(nt & 1) * 2 + 1];
                    mma_fp16(acc[mt][nt], ah[mt], b0h, b1h);
                    mma_fp16(acc[mt][nt], ah[mt], b0l, b1l);
                }
        }
        __syncthreads();
    }

    const int g = lane >> 2, tig = lane & 3;
#pragma unroll
    for (int mt = 0; mt < 2; mt++) {
#pragma unroll
        for (int nt = 0; nt < 4; nt++) {
            int row = bm + wm * 32 + mt * 16 + g;
            int col = wn * 32 + nt * 8 + tig * 2;
            size_t o0 = coff + (size_t)row * ldc + col;
            size_t o1 = coff + (size_t)(row + 8) * ldc + col;
            __half2 p0 = __floats2half2_rn(acc[mt][nt][0], acc[mt][nt][1]);
            __half2 p1 = __floats2half2_rn(acc[mt][nt][2], acc[mt][nt][3]);
            *(uint32_t*)&Co[o0] = *(uint32_t*)&p0;
            *(uint32_t*)&Co[o1] = *(uint32_t*)&p1;
        }
    }
}

// ======================================================================
// Fused softmax + avg + fp16 attn: 256 thr = 8 warps; warp w owns heads
// {2w, 2w+1} sequentially. Reads fp16 scores. Warp-shuffle reductions;
// warp-private smem avg slices; one barrier; 8-way column reduction.
// ======================================================================
#define SM_SMEM (8 * S_ * 4)   // 64 KB

__global__ void __launch_bounds__(256)
softmax_avg(const __half* __restrict__ SC, __half* __restrict__ P,
            float* __restrict__ avg)
{
    extern __shared__ float avg_s[];   // [8][S_]
    const int bq = blockIdx.x;
    const int b = bq >> 11, q = bq & 2047;
    const int tid = threadIdx.x;
    const int warp = tid >> 5, lane = tid & 31;

    float* slice = avg_s + warp * S_;
#pragma unroll
    for (int i = 0; i < 16; i++)
        *(float4*)&slice[lane * 4 + i * 128] = make_float4(0.f, 0.f, 0.f, 0.f);

#pragma unroll 1
    for (int hh = 0; hh < 2; hh++) {
        const int h = warp * 2 + hh;
        size_t off = (((size_t)b * H_ + h) * S_ + q) * (size_t)S_;

        float v[64];
        float mx = -INFINITY;
#pragma unroll
        for (int i = 0; i < 8; i++) {
            uint4 t = *(const uint4*)(SC + off + lane * 8 + i * 256);
            const __half2* hp = (const __half2*)&t;
#pragma unroll
            for (int j = 0; j < 4; j++) {
                float2 f = __half22float2(hp[j]);
                v[8 * i + 2 * j]     = f.x;
                v[8 * i + 2 * j + 1] = f.y;
                mx = fmaxf(mx, fmaxf(f.x, f.y));
            }
        }
#pragma unroll
        for (int o = 16; o; o >>= 1) mx = fmaxf(mx, __shfl_xor_sync(0xffffffffu, mx, o));

        float s = 0.f;
#pragma unroll
        for (int i = 0; i < 64; i++) { v[i] = __expf(v[i] - mx); s += v[i]; }
#pragma unroll
        for (int o = 16; o; o >>= 1) s += __shfl_xor_sync(0xffffffffu, s, o);
        float inv = 1.0f / s;

#pragma unroll
        for (int i = 0; i < 8; i++) {
            int c = lane * 8 + i * 256;
            float p[8];
#pragma unroll
            for (int j = 0; j < 8; j++) p[j] = v[8 * i + j] * inv;
            float4 a0 = *(float4*)&slice[c];
            float4 a1 = *(float4*)&slice[c + 4];
            a0.x += p[0]; a0.y += p[1]; a0.z += p[2]; a0.w += p[3];
            a1.x += p[4]; a1.y += p[5]; a1.z += p[6]; a1.w += p[7];
            *(float4*)&slice[c] = a0;
            *(float4*)&slice[c + 4] = a1;
            __half2 q0 = __floats2half2_rn(p[0], p[1]);
            __half2 q1 = __floats2half2_rn(p[2], p[3]);
            __half2 q2 = __floats2half2_rn(p[4], p[5]);
            __half2 q3 = __floats2half2_rn(p[6], p[7]);
            uint4 pk = make_uint4(*(uint32_t*)&q0, *(uint32_t*)&q1,
                                  *(uint32_t*)&q2, *(uint32_t*)&q3);
            *(uint4*)&P[off + c] = pk;
        }
    }
    __syncthreads();

    const float ih = 1.0f / H_;
    size_t ao = ((size_t)b * S_ + q) * (size_t)S_;
#pragma unroll
    for (int blk = 0; blk < 2; blk++) {
        int c = tid * 4 + blk * 1024;
        float4 s0 = *(float4*)&avg_s[0 * S_ + c];
#pragma unroll
        for (int w = 1; w < 8; w++) {
            float4 sw = *(float4*)&avg_s[w * S_ + c];
            s0.x += sw.x; s0.y += sw.y; s0.z += sw.z; s0.w += sw.w;
        }
        s0.x *= ih; s0.y *= ih; s0.z *= ih; s0.w *= ih;
        *(float4*)(avg + ao + c) = s0;
    }
}

// ======================================================================
extern "C" void kernel_launch(void* const* d_in, const int* in_sizes, int n_in,
                              void* d_out, int out_size)
{
    const float* query = (const float*)d_in[0];
    const float* Wq = (const float*)d_in[1];
    const float* bq = (const float*)d_in[2];
    const float* Wk = (const float*)d_in[3];
    const float* bk = (const float*)d_in[4];
    const float* Wv = (const float*)d_in[5];
    const float* bv = (const float*)d_in[6];
    const float* Wo = (const float*)d_in[7];
    const float* bo = (const float*)d_in[8];
    float* out = (float*)d_out;

    __half *xf, *Wfh, *Wfl, *QKVh, *QKVl, *cf, *P, *SC16;
    float *bias3;
    cudaGetSymbolAddress((void**)&xf, g_xf);
    cudaGetSymbolAddress((void**)&Wfh, g_Wfh); cudaGetSymbolAddress((void**)&Wfl, g_Wfl);
    cudaGetSymbolAddress((void**)&QKVh, g_QKVh); cudaGetSymbolAddress((void**)&QKVl, g_QKVl);
    cudaGetSymbolAddress((void**)&cf, g_cf);
    cudaGetSymbolAddress((void**)&P, g_P);
    cudaGetSymbolAddress((void**)&SC16, g_scores);
    cudaGetSymbolAddress((void**)&bias3, g_bias3);

    cudaFuncSetAttribute(gemm_nt_f16, cudaFuncAttributeMaxDynamicSharedMemorySize, F2_SMEM);
    cudaFuncSetAttribute(gemm_pv,     cudaFuncAttributeMaxDynamicSharedMemorySize, NN_SMEM);
    cudaFuncSetAttribute(softmax_avg, cudaFuncAttributeMaxDynamicSharedMemorySize, SM_SMEM);

    const int M = B_ * S_;                 // 4096
    const size_t DD = (size_t)D_ * D_;
    const int N3 = 3 * D_;                 // 3072

    // ---- operand splits + bias concat ----
    split_query<<<(B_ * S_ * D_) / 256, 256>>>(query, xf);
    split_weights<<<(D_ * D_) / 256, 256>>>(Wq, Wk, Wv, Wo, Wfh, Wfl);
    concat_bias<<<D_ / 256, 256>>>(bq, bk, bv, bias3);

    // ---- merged QKV projection fp16x2 -> fp16 hi/lo ----
    gemm_nt_f16<<<dim3(N3 / 128, M / 128, 1), 256, F2_SMEM>>>(
        xf, D_, Wfh, Wfl, D_,
        nullptr, nullptr, QKVh, QKVl, N3, D_, 1.f, bias3,
        1, 0, 0, 0, 0, 0, 0);

    // ---- scores = (Q @ K^T)/8 -> fp16. A = Q fp16 single (hi array),
    //      B = K fp16 hi/lo. Batched z = b*H+h. ----
    gemm_nt_f16<<<dim3(S_ / 128, S_ / 128, B_ * H_), 256, F2_SMEM>>>(
        QKVh, N3, QKVh + D_, QKVl + D_, N3,
        nullptr, SC16, nullptr, nullptr, S_, HD_, 0.125f, nullptr,
        H_,
        (size_t)S_ * N3, HD_,
        (size_t)S_ * N3, HD_,
        (size_t)H_ * S_ * S_, (size_t)S_ * S_);

    // ---- fused softmax + avg + fp16 attn ----
    softmax_avg<<<B_ * S_, 256, SM_SMEM>>>(SC16, P, out + (size_t)M * D_);

    // ---- ctx = P @ V -> fp16 single ----
    gemm_pv<<<dim3(1, S_ / 128, B_ * H_), 256, NN_SMEM>>>(
        P, S_,
        QKVh + 2 * D_, QKVl + 2 * D_, N3,
        cf, D_, S_,
        H_,
        (size_t)H_ * S_ * S_, (size_t)S_ * S_,
        (size_t)S_ * N3, HD_,
        (size_t)S_ * D_, HD_);

    // ---- output projection fp16x2 -> fp32 out ----
    gemm_nt_f16<<<dim3(D_ / 128, M / 128, 1), 256, F2_SMEM>>>(
        cf, D_, Wfh + 3 * DD, Wfl + 3 * DD, D_,
        out, nullptr, nullptr, nullptr, D_, D_, 1.f, bo,
        1, 0, 0, 0, 0, 0, 0);
}

// round 17
// speedup vs baseline: 1.2049x; 1.2049x over previous
#include <cuda_runtime.h>
#include <cuda_bf16.h>
#include <cuda_fp16.h>
#include <math.h>
#include <stdint.h>

#define B_  2
#define S_  2048
#define D_  1024
#define H_  16
#define HD_ 64

// ---------------- scratch (no cudaMalloc allowed) ----------------
__device__ __half g_xf[(size_t)B_ * S_ * D_];                             // x fp16 single
__device__ __half g_Wfh[(size_t)4 * D_ * D_], g_Wfl[(size_t)4 * D_ * D_]; // Wq,k,v,o fp16 hi/lo
__device__ float g_bias3[3 * D_];
__device__ __half g_QKVh[(size_t)B_ * S_ * 3 * D_], g_QKVl[(size_t)B_ * S_ * 3 * D_];
__device__ __half g_cf[(size_t)B_ * S_ * D_];                             // ctx fp16 single
__device__ __half g_P[(size_t)B_ * H_ * S_ * S_];       // attn probs fp16
__device__ __half g_scores[(size_t)B_ * H_ * S_ * S_];  // scores fp16 (268 MB)

// ======================= PTX helpers =======================
__device__ __forceinline__ uint32_t sptr(const void* p) {
    return (uint32_t)__cvta_generic_to_shared(p);
}
__device__ __forceinline__ void cpa16(uint32_t dst, const void* src) {
    asm volatile("cp.async.cg.shared.global [%0], [%1], 16;" :: "r"(dst), "l"(src));
}
__device__ __forceinline__ void cpa_commit() {
    asm volatile("cp.async.commit_group;");
}
template<int N> __device__ __forceinline__ void cpa_wait() {
    asm volatile("cp.async.wait_group %0;" :: "n"(N));
}
__device__ __forceinline__ void ldm_x4(uint32_t (&r)[4], uint32_t addr) {
    asm volatile("ldmatrix.sync.aligned.m8n8.x4.shared.b16 {%0,%1,%2,%3}, [%4];"
                 : "=r"(r[0]), "=r"(r[1]), "=r"(r[2]), "=r"(r[3]) : "r"(addr));
}
__device__ __forceinline__ void ldm_x4t(uint32_t (&r)[4], uint32_t addr) {
    asm volatile("ldmatrix.sync.aligned.m8n8.x4.trans.shared.b16 {%0,%1,%2,%3}, [%4];"
                 : "=r"(r[0]), "=r"(r[1]), "=r"(r[2]), "=r"(r[3]) : "r"(addr));
}
__device__ __forceinline__ void mma_fp16(float (&c)[4], const uint32_t (&a)[4],
                                         uint32_t b0, uint32_t b1) {
    asm volatile(
        "mma.sync.aligned.m16n8k16.row.col.f32.f16.f16.f32 "
        "{%0,%1,%2,%3}, {%4,%5,%6,%7}, {%8,%9}, {%0,%1,%2,%3};"
        : "+f"(c[0]), "+f"(c[1]), "+f"(c[2]), "+f"(c[3])
        : "r"(a[0]), "r"(a[1]), "r"(a[2]), "r"(a[3]), "r"(b0), "r"(b1));
}
__device__ __forceinline__ void splitu_fp16(float x, uint16_t& h, uint16_t& l) {
    __half hh = __float2half(x);
    __half ll = __float2half(x - __half2float(hh));
    h = *(uint16_t*)&hh; l = *(uint16_t*)&ll;
}

// ======================================================================
// split / bias kernels
// ======================================================================
__global__ void __launch_bounds__(256)
split_query(const float* __restrict__ x, __half* __restrict__ xf)
{
    size_t i = (size_t)blockIdx.x * 256 + threadIdx.x;
    xf[i] = __float2half(x[i]);
}

__global__ void __launch_bounds__(256)
split_weights(const float* __restrict__ Wq, const float* __restrict__ Wk,
              const float* __restrict__ Wv, const float* __restrict__ Wo,
              __half* __restrict__ Wfh, __half* __restrict__ Wfl)
{
    size_t i = (size_t)blockIdx.x * 256 + threadIdx.x;   // < D*D
    const size_t n = (size_t)D_ * D_;
    uint16_t h, l;
    splitu_fp16(Wq[i], h, l); Wfh[i]       = *(__half*)&h; Wfl[i]       = *(__half*)&l;
    splitu_fp16(Wk[i], h, l); Wfh[i + n]   = *(__half*)&h; Wfl[i + n]   = *(__half*)&l;
    splitu_fp16(Wv[i], h, l); Wfh[i + 2*n] = *(__half*)&h; Wfl[i + 2*n] = *(__half*)&l;
    splitu_fp16(Wo[i], h, l); Wfh[i + 3*n] = *(__half*)&h; Wfl[i + 3*n] = *(__half*)&l;
}

__global__ void __launch_bounds__(256)
concat_bias(const float* __restrict__ a, const float* __restrict__ b,
            const float* __restrict__ c, float* __restrict__ o)
{
    int i = blockIdx.x * 256 + threadIdx.x;   // < D_
    o[i] = a[i]; o[D_ + i] = b[i]; o[2 * D_ + i] = c[i];
}

// ======================================================================
// fp16x2 GEMM mainloop (shared by the three nt kernels via macro body).
// A fp16 single [M,K], B fp16 hi/lo [N,K]. 2 MMAs per tile.
// k-chunk 32, 2 stages, proven-safe loop. 8 warps (2x4), warp 64x32.
// Stage 30720B: A@0, BH@10240, BL@20480; 80B pitch.
// ======================================================================
#define F2_STG  30720
#define F2_SMEM (2 * F2_STG)

#define F2_MAINLOOP(Ag, lda, Bgh, Bgl, ldb, K)                                \
    float acc[4][4][4];                                                       \
    _Pragma("unroll")                                                         \
    for (int i = 0; i < 4; i++)                                               \
        _Pragma("unroll")                                                     \
        for (int j = 0; j < 4; j++)                                           \
            _Pragma("unroll")                                                 \
            for (int l = 0; l < 4; l++) acc[i][j][l] = 0.f;                   \
    const int KT = (K) >> 5;                                                  \
    auto issue = [&](int kt, int st) {                                        \
        uint32_t base = sb + st * F2_STG;                                     \
        int k0 = kt * 32;                                                     \
        _Pragma("unroll")                                                     \
        for (int i = 0; i < 6; i++) {                                         \
            int ch = i * 256 + tid;                                           \
            int arr = ch >> 9;                                                \
            int row = (ch & 511) >> 2;                                        \
            int c16 = ch & 3;                                                 \
            uint32_t dst = base + arr * 10240 + row * 80 + c16 * 16;          \
            const __half* src;                                                \
            int col = k0 + c16 * 8;                                           \
            if (arr == 0)      src = (Ag)  + (size_t)(bm + row) * (lda) + col;\
            else if (arr == 1) src = (Bgh) + (size_t)(bn + row) * (ldb) + col;\
            else               src = (Bgl) + (size_t)(bn + row) * (ldb) + col;\
            cpa16(dst, src);                                                  \
        }                                                                     \
        cpa_commit();                                                         \
    };                                                                        \
    issue(0, 0);                                                              \
    for (int kt = 0; kt < KT; kt++) {                                         \
        int st = kt & 1;                                                      \
        if (kt + 1 < KT) { issue(kt + 1, st ^ 1); cpa_wait<1>(); }            \
        else             { cpa_wait<0>(); }                                   \
        __syncthreads();                                                      \
        uint32_t base = sb + st * F2_STG;                                     \
        _Pragma("unroll")                                                     \
        for (int ks = 0; ks < 2; ks++) {                                      \
            uint32_t ah[4][4];                                                \
            {                                                                 \
                int arow = wm * 64 + (lane & 15);                             \
                uint32_t ac = ks * 32 + (lane >> 4) * 16;                     \
                _Pragma("unroll")                                             \
                for (int mt = 0; mt < 4; mt++)                                \
                    ldm_x4(ah[mt], base + (uint32_t)(arow + mt * 16) * 80 + ac);\
            }                                                                 \
            uint32_t bh[2][4], bl[2][4];                                      \
            {                                                                 \
                int brow0 = wn * 32 + (lane & 7) + ((lane >> 4) & 1) * 8;     \
                uint32_t bc = ((lane >> 3) & 1) * 16 + ks * 32;               \
                _Pragma("unroll")                                             \
                for (int pr = 0; pr < 2; pr++) {                              \
                    uint32_t ro = (uint32_t)(brow0 + pr * 16) * 80 + bc;      \
                    ldm_x4(bh[pr], base + 10240 + ro);                        \
                    ldm_x4(bl[pr], base + 20480 + ro);                        \
                }                                                             \
            }                                                                 \
            _Pragma("unroll")                                                 \
            for (int mt = 0; mt < 4; mt++)                                    \
                _Pragma("unroll")                                             \
                for (int nt = 0; nt < 4; nt++) {                              \
                    uint32_t b0h = bh[nt >> 1][(nt & 1) * 2];                 \
                    uint32_t b1h = bh[nt >> 1][(nt & 1) * 2 + 1];             \
                    uint32_t b0l = bl[nt >> 1][(nt & 1) * 2];                 \
                    uint32_t b1l = bl[nt >> 1][(nt & 1) * 2 + 1];             \
                    mma_fp16(acc[mt][nt], ah[mt], b0h, b1h);                  \
                    mma_fp16(acc[mt][nt], ah[mt], b0l, b1l);                  \
                }                                                             \
        }                                                                     \
        __syncthreads();                                                      \
    }

// ---- QKV: split fp16 hi/lo output + bias ----
__global__ void __launch_bounds__(256, 2)
gemm_qkv(const __half* __restrict__ Ag, int lda,
         const __half* __restrict__ Bgh, const __half* __restrict__ Bgl, int ldb,
         __half* __restrict__ Coh, __half* __restrict__ Col,
         int ldc, int K, const float* __restrict__ bias)
{
    extern __shared__ char dsm[];
    const uint32_t sb = sptr(dsm);
    const int bm = blockIdx.y * 128;
    const int bn = blockIdx.x * 128;
    const int tid = threadIdx.x;
    const int warp = tid >> 5, lane = tid & 31;
    const int wm = warp >> 2, wn = warp & 3;

    F2_MAINLOOP(Ag, lda, Bgh, Bgl, ldb, K)

    const int g = lane >> 2, tig = lane & 3;
#pragma unroll
    for (int mt = 0; mt < 4; mt++) {
#pragma unroll
        for (int nt = 0; nt < 4; nt++) {
            int row = bm + wm * 64 + mt * 16 + g;
            int col = bn + wn * 32 + nt * 8 + tig * 2;
            float b0 = bias[col], b1 = bias[col + 1];
            float v00 = acc[mt][nt][0] + b0;
            float v01 = acc[mt][nt][1] + b1;
            float v10 = acc[mt][nt][2] + b0;
            float v11 = acc[mt][nt][3] + b1;
            size_t o0 = (size_t)row * ldc + col;
            size_t o1 = (size_t)(row + 8) * ldc + col;
            uint16_t h0, l0, h1, l1;
            splitu_fp16(v00, h0, l0); splitu_fp16(v01, h1, l1);
            *(uint32_t*)&Coh[o0] = (uint32_t)h0 | ((uint32_t)h1 << 16);
            *(uint32_t*)&Col[o0] = (uint32_t)l0 | ((uint32_t)l1 << 16);
            splitu_fp16(v10, h0, l0); splitu_fp16(v11, h1, l1);
            *(uint32_t*)&Coh[o1] = (uint32_t)h0 | ((uint32_t)h1 << 16);
            *(uint32_t*)&Col[o1] = (uint32_t)l0 | ((uint32_t)l1 << 16);
        }
    }
}

// ---- scores: fp16 single output, alpha scale, batched z = b*H + h ----
__global__ void __launch_bounds__(256, 2)
gemm_scores(const __half* __restrict__ Ag, int lda,
            const __half* __restrict__ Bgh, const __half* __restrict__ Bgl, int ldb,
            __half* __restrict__ C16, int ldc, int K, float alpha,
            size_t sA1, size_t sA2, size_t sC2)
{
    extern __shared__ char dsm[];
    int z = blockIdx.z;
    int z1 = z >> 4, z2 = z & 15;          // batch, head
    size_t aoff = z1 * sA1 + z2 * sA2;
    const __half* Agz  = Ag  + aoff;
    const __half* Bghz = Bgh + aoff;       // K ptr already offset by +D_ at launch
    const __half* Bglz = Bgl + aoff;
    size_t coff = (size_t)z * sC2;

    const uint32_t sb = sptr(dsm);
    const int bm = blockIdx.y * 128;
    const int bn = blockIdx.x * 128;
    const int tid = threadIdx.x;
    const int warp = tid >> 5, lane = tid & 31;
    const int wm = warp >> 2, wn = warp & 3;

    F2_MAINLOOP(Agz, lda, Bghz, Bglz, ldb, K)

    const int g = lane >> 2, tig = lane & 3;
#pragma unroll
    for (int mt = 0; mt < 4; mt++) {
#pragma unroll
        for (int nt = 0; nt < 4; nt++) {
            int row = bm + wm * 64 + mt * 16 + g;
            int col = bn + wn * 32 + nt * 8 + tig * 2;
            size_t o0 = coff + (size_t)row * ldc + col;
            size_t o1 = coff + (size_t)(row + 8) * ldc + col;
            __half2 p0 = __floats2half2_rn(alpha * acc[mt][nt][0], alpha * acc[mt][nt][1]);
            __half2 p1 = __floats2half2_rn(alpha * acc[mt][nt][2], alpha * acc[mt][nt][3]);
            *(uint32_t*)&C16[o0] = *(uint32_t*)&p0;
            *(uint32_t*)&C16[o1] = *(uint32_t*)&p1;
        }
    }
}

// ---- out-proj: fp32 output + bias ----
__global__ void __launch_bounds__(256, 2)
gemm_oproj(const __half* __restrict__ Ag, int lda,
           const __half* __restrict__ Bgh, const __half* __restrict__ Bgl, int ldb,
           float* __restrict__ Cf, int ldc, int K, const float* __restrict__ bias)
{
    extern __shared__ char dsm[];
    const uint32_t sb = sptr(dsm);
    const int bm = blockIdx.y * 128;
    const int bn = blockIdx.x * 128;
    const int tid = threadIdx.x;
    const int warp = tid >> 5, lane = tid & 31;
    const int wm = warp >> 2, wn = warp & 3;

    F2_MAINLOOP(Ag, lda, Bgh, Bgl, ldb, K)

    const int g = lane >> 2, tig = lane & 3;
#pragma unroll
    for (int mt = 0; mt < 4; mt++) {
#pragma unroll
        for (int nt = 0; nt < 4; nt++) {
            int row = bm + wm * 64 + mt * 16 + g;
            int col = bn + wn * 32 + nt * 8 + tig * 2;
            float b0 = bias[col], b1 = bias[col + 1];
            size_t o0 = (size_t)row * ldc + col;
            size_t o1 = (size_t)(row + 8) * ldc + col;
            *(float2*)&Cf[o0] = make_float2(acc[mt][nt][0] + b0, acc[mt][nt][1] + b1);
            *(float2*)&Cf[o1] = make_float2(acc[mt][nt][2] + b0, acc[mt][nt][3] + b1);
        }
    }
}

// ======================================================================
// PV GEMM: ctx = P @ V. P fp16 single, V fp16 hi/lo. 2 MMAs per tile.
// k-chunk 32, 2 stages, proven-safe loop. 8 warps (4x2), warp 32x32.
// Stage (19456B): P@0 (128x80B), VH@10240 (32x144B), VL@14848.
// Output: ctx fp16 single.
// ======================================================================
#define NN_STG  19456
#define NN_SMEM (2 * NN_STG)

__global__ void __launch_bounds__(256, 2)
gemm_pv(const __half* __restrict__ P, int lda,
        const __half* __restrict__ Vgh, const __half* __restrict__ Vgl, int ldb,
        __half* __restrict__ Co, int ldc,
        int K, int zdiv,
        size_t sA1, size_t sA2, size_t sB1, size_t sB2, size_t sC1, size_t sC2)
{
    extern __shared__ char dsm[];
    int z = blockIdx.z;
    int z1 = z / zdiv, z2 = z % zdiv;
    P   += z1 * sA1 + z2 * sA2;
    Vgh += z1 * sB1 + z2 * sB2;  Vgl += z1 * sB1 + z2 * sB2;
    size_t coff = z1 * sC1 + z2 * sC2;

    const uint32_t sb = sptr(dsm);
    const int bm = blockIdx.y * 128;
    const int tid = threadIdx.x;
    const int warp = tid >> 5, lane = tid & 31;
    const int wm = warp >> 1, wn = warp & 1;

    float acc[2][4][4];
#pragma unroll
    for (int i = 0; i < 2; i++)
#pragma unroll
        for (int j = 0; j < 4; j++)
#pragma unroll
            for (int l = 0; l < 4; l++) acc[i][j][l] = 0.f;

    const int KT = K >> 5;

    auto issue = [&](int kt, int st) {
        uint32_t base = sb + st * NN_STG;
        int k0 = kt * 32;
#pragma unroll
        for (int i = 0; i < 2; i++) {
            int ch = i * 256 + tid;
            int row = ch >> 2, c16 = ch & 3;
            const __half* src = P + (size_t)(bm + row) * lda + k0 + c16 * 8;
            cpa16(base + row * 80 + c16 * 16, src);
        }
#pragma unroll
        for (int i = 0; i < 2; i++) {
            int ch = i * 256 + tid;
            int arr = ch >> 8, row = (ch & 255) >> 3, c16 = ch & 7;
            const __half* src = (arr ? Vgl : Vgh) + (size_t)(k0 + row) * ldb + c16 * 8;
            cpa16(base + 10240 + arr * 4608 + row * 144 + c16 * 16, src);
        }
        cpa_commit();
    };

    issue(0, 0);

    for (int kt = 0; kt < KT; kt++) {
        int st = kt & 1;
        if (kt + 1 < KT) { issue(kt + 1, st ^ 1); cpa_wait<1>(); }
        else             { cpa_wait<0>(); }
        __syncthreads();

        uint32_t base = sb + st * NN_STG;
#pragma unroll
        for (int ks = 0; ks < 2; ks++) {
            uint32_t ah[2][4];
            {
                int arow = wm * 32 + (lane & 15);
                uint32_t ac = ks * 32 + (lane >> 4) * 16;
#pragma unroll
                for (int mt = 0; mt < 2; mt++)
                    ldm_x4(ah[mt], base + (uint32_t)(arow + mt * 16) * 80 + ac);
            }
            uint32_t bh[2][4], bl[2][4];
            {
                int l16 = lane & 15, hi = lane >> 4;
                uint32_t rowoff = (uint32_t)(ks * 16 + l16) * 144;
#pragma unroll
                for (int pr = 0; pr < 2; pr++) {
                    uint32_t co = (wn * 32 + pr * 16 + hi * 8) * 2;
                    ldm_x4t(bh[pr], base + 10240 + rowoff + co);
                    ldm_x4t(bl[pr], base + 14848 + rowoff + co);
                }
            }
#pragma unroll
            for (int mt = 0; mt < 2; mt++)
#pragma unroll
                for (int nt = 0; nt < 4; nt++) {
                    uint32_t b0h = bh[nt >> 1][(nt & 1) * 2];
                    uint32_t b1h = bh[nt >> 1][(nt & 1) * 2 + 1];
                    uint32_t b0l = bl[nt >> 1][(nt & 1) * 2];
                    uint32_t b1l = bl[nt >> 1][(nt & 1) * 2 + 1];
                    mma_fp16(acc[mt][nt], ah[mt], b0h, b1h);
                    mma_fp16(acc[mt][nt], ah[mt], b0l, b1l);
                }
        }
        __syncthreads();
    }

    const int g = lane >> 2, tig = lane & 3;
#pragma unroll
    for (int mt = 0; mt < 2; mt++) {
#pragma unroll
        for (int nt = 0; nt < 4; nt++) {
            int row = bm + wm * 32 + mt * 16 + g;
            int col = wn * 32 + nt * 8 + tig * 2;
            size_t o0 = coff + (size_t)row * ldc + col;
            size_t o1 = coff + (size_t)(row + 8) * ldc + col;
            __half2 p0 = __floats2half2_rn(acc[mt][nt][0], acc[mt][nt][1]);
            __half2 p1 = __floats2half2_rn(acc[mt][nt][2], acc[mt][nt][3]);
            *(uint32_t*)&Co[o0] = *(uint32_t*)&p0;
            *(uint32_t*)&Co[o1] = *(uint32_t*)&p1;
        }
    }
}

// ======================================================================
// Fused softmax + avg + fp16 attn: 256 thr = 8 warps; warp w owns heads
// {2w, 2w+1} sequentially. Reads fp16 scores. Warp-shuffle reductions;
// warp-private smem avg slices; one barrier; 8-way column reduction.
// ======================================================================
#define SM_SMEM (8 * S_ * 4)   // 64 KB

__global__ void __launch_bounds__(256)
softmax_avg(const __half* __restrict__ SC, __half* __restrict__ P,
            float* __restrict__ avg)
{
    extern __shared__ float avg_s[];   // [8][S_]
    const int bq = blockIdx.x;
    const int b = bq >> 11, q = bq & 2047;
    const int tid = threadIdx.x;
    const int warp = tid >> 5, lane = tid & 31;

    float* slice = avg_s + warp * S_;
#pragma unroll
    for (int i = 0; i < 16; i++)
        *(float4*)&slice[lane * 4 + i * 128] = make_float4(0.f, 0.f, 0.f, 0.f);

#pragma unroll 1
    for (int hh = 0; hh < 2; hh++) {
        const int h = warp * 2 + hh;
        size_t off = (((size_t)b * H_ + h) * S_ + q) * (size_t)S_;

        float v[64];
        float mx = -INFINITY;
#pragma unroll
        for (int i = 0; i < 8; i++) {
            uint4 t = *(const uint4*)(SC + off + lane * 8 + i * 256);
            const __half2* hp = (const __half2*)&t;
#pragma unroll
            for (int j = 0; j < 4; j++) {
                float2 f = __half22float2(hp[j]);
                v[8 * i + 2 * j]     = f.x;
                v[8 * i + 2 * j + 1] = f.y;
                mx = fmaxf(mx, fmaxf(f.x, f.y));
            }
        }
#pragma unroll
        for (int o = 16; o; o >>= 1) mx = fmaxf(mx, __shfl_xor_sync(0xffffffffu, mx, o));

        float s = 0.f;
#pragma unroll
        for (int i = 0; i < 64; i++) { v[i] = __expf(v[i] - mx); s += v[i]; }
#pragma unroll
        for (int o = 16; o; o >>= 1) s += __shfl_xor_sync(0xffffffffu, s, o);
        float inv = 1.0f / s;

#pragma unroll
        for (int i = 0; i < 8; i++) {
            int c = lane * 8 + i * 256;
            float p[8];
#pragma unroll
            for (int j = 0; j < 8; j++) p[j] = v[8 * i + j] * inv;
            float4 a0 = *(float4*)&slice[c];
            float4 a1 = *(float4*)&slice[c + 4];
            a0.x += p[0]; a0.y += p[1]; a0.z += p[2]; a0.w += p[3];
            a1.x += p[4]; a1.y += p[5]; a1.z += p[6]; a1.w += p[7];
            *(float4*)&slice[c] = a0;
            *(float4*)&slice[c + 4] = a1;
            __half2 q0 = __floats2half2_rn(p[0], p[1]);
            __half2 q1 = __floats2half2_rn(p[2], p[3]);
            __half2 q2 = __floats2half2_rn(p[4], p[5]);
            __half2 q3 = __floats2half2_rn(p[6], p[7]);
            uint4 pk = make_uint4(*(uint32_t*)&q0, *(uint32_t*)&q1,
                                  *(uint32_t*)&q2, *(uint32_t*)&q3);
            *(uint4*)&P[off + c] = pk;
        }
    }
    __syncthreads();

    const float ih = 1.0f / H_;
    size_t ao = ((size_t)b * S_ + q) * (size_t)S_;
#pragma unroll
    for (int blk = 0; blk < 2; blk++) {
        int c = tid * 4 + blk * 1024;
        float4 s0 = *(float4*)&avg_s[0 * S_ + c];
#pragma unroll
        for (int w = 1; w < 8; w++) {
            float4 sw = *(float4*)&avg_s[w * S_ + c];
            s0.x += sw.x; s0.y += sw.y; s0.z += sw.z; s0.w += sw.w;
        }
        s0.x *= ih; s0.y *= ih; s0.z *= ih; s0.w *= ih;
        *(float4*)(avg + ao + c) = s0;
    }
}

// ======================================================================
extern "C" void kernel_launch(void* const* d_in, const int* in_sizes, int n_in,
                              void* d_out, int out_size)
{
    const float* query = (const float*)d_in[0];
    const float* Wq = (const float*)d_in[1];
    const float* bq = (const float*)d_in[2];
    const float* Wk = (const float*)d_in[3];
    const float* bk = (const float*)d_in[4];
    const float* Wv = (const float*)d_in[5];
    const float* bv = (const float*)d_in[6];
    const float* Wo = (const float*)d_in[7];
    const float* bo = (const float*)d_in[8];
    float* out = (float*)d_out;

    __half *xf, *Wfh, *Wfl, *QKVh, *QKVl, *cf, *P, *SC16;
    float *bias3;
    cudaGetSymbolAddress((void**)&xf, g_xf);
    cudaGetSymbolAddress((void**)&Wfh, g_Wfh); cudaGetSymbolAddress((void**)&Wfl, g_Wfl);
    cudaGetSymbolAddress((void**)&QKVh, g_QKVh); cudaGetSymbolAddress((void**)&QKVl, g_QKVl);
    cudaGetSymbolAddress((void**)&cf, g_cf);
    cudaGetSymbolAddress((void**)&P, g_P);
    cudaGetSymbolAddress((void**)&SC16, g_scores);
    cudaGetSymbolAddress((void**)&bias3, g_bias3);

    cudaFuncSetAttribute(gemm_qkv,    cudaFuncAttributeMaxDynamicSharedMemorySize, F2_SMEM);
    cudaFuncSetAttribute(gemm_scores, cudaFuncAttributeMaxDynamicSharedMemorySize, F2_SMEM);
    cudaFuncSetAttribute(gemm_oproj,  cudaFuncAttributeMaxDynamicSharedMemorySize, F2_SMEM);
    cudaFuncSetAttribute(gemm_pv,     cudaFuncAttributeMaxDynamicSharedMemorySize, NN_SMEM);
    cudaFuncSetAttribute(softmax_avg, cudaFuncAttributeMaxDynamicSharedMemorySize, SM_SMEM);

    const int M = B_ * S_;                 // 4096
    const size_t DD = (size_t)D_ * D_;
    const int N3 = 3 * D_;                 // 3072

    // ---- operand splits + bias concat ----
    split_query<<<(B_ * S_ * D_) / 256, 256>>>(query, xf);
    split_weights<<<(D_ * D_) / 256, 256>>>(Wq, Wk, Wv, Wo, Wfh, Wfl);
    concat_bias<<<D_ / 256, 256>>>(bq, bk, bv, bias3);

    // ---- merged QKV projection fp16x2 -> fp16 hi/lo ----
    gemm_qkv<<<dim3(N3 / 128, M / 128, 1), 256, F2_SMEM>>>(
        xf, D_, Wfh, Wfl, D_, QKVh, QKVl, N3, D_, bias3);

    // ---- scores = (Q @ K^T)/8 -> fp16, Q single / K hi+lo, z = b*H+h ----
    gemm_scores<<<dim3(S_ / 128, S_ / 128, B_ * H_), 256, F2_SMEM>>>(
        QKVh, N3, QKVh + D_, QKVl + D_, N3,
        SC16, S_, HD_, 0.125f,
        (size_t)S_ * N3, HD_, (size_t)S_ * S_);

    // ---- fused softmax + avg + fp16 attn ----
    softmax_avg<<<B_ * S_, 256, SM_SMEM>>>(SC16, P, out + (size_t)M * D_);

    // ---- ctx = P @ V -> fp16 single ----
    gemm_pv<<<dim3(1, S_ / 128, B_ * H_), 256, NN_SMEM>>>(
        P, S_,
        QKVh + 2 * D_, QKVl + 2 * D_, N3,
        cf, D_, S_,
        H_,
        (size_t)H_ * S_ * S_, (size_t)S_ * S_,
        (size_t)S_ * N3, HD_,
        (size_t)S_ * D_, HD_);

    // ---- output projection fp16x2 -> fp32 out ----
    gemm_oproj<<<dim3(D_ / 128, M / 128, 1), 256, F2_SMEM>>>(
        cf, D_, Wfh + 3 * DD, Wfl + 3 * DD, D_,
        out, D_, D_, bo);
}